// round 3
// baseline (speedup 1.0000x reference)
#include <cuda_runtime.h>
#include <math.h>

// Problem dims
#define Bq   128
#define Sq   256
#define Eq   512
#define Hq   1024
#define Vq   2048
#define G4H  4096   // 4*H

// ---------------------------------------------------------------------------
// Scratch (device globals; no allocation allowed)
// ---------------------------------------------------------------------------
__device__ float g_embWf[Vq * G4H];          // 32 MB: emb@Wf + bf
__device__ float g_embWb[Vq * G4H];          // 32 MB: emb@Wb + bb
__device__ float g_h[2][2][Bq * Hq];         // [pingpong][dir]  (2 MB)
__device__ float g_c[2][Bq * Hq];            // [dir]            (1 MB)
__device__ float g_hcat[Bq * Sq * 2 * Hq];   // [B][S][2H]       (256 MB)

// ---------------------------------------------------------------------------
// f32x2 packed-FMA helpers (Blackwell: fma.rn.f32x2, PTX-only)
// ---------------------------------------------------------------------------
__device__ __forceinline__ unsigned long long dup2(float x) {
    unsigned long long r;
    asm("mov.b64 %0, {%1, %1};" : "=l"(r) : "f"(x));
    return r;
}
__device__ __forceinline__ void ffma2(unsigned long long &acc,
                                      unsigned long long a,
                                      unsigned long long b) {
    asm("fma.rn.f32x2 %0, %1, %2, %0;" : "+l"(acc) : "l"(a), "l"(b));
}
__device__ __forceinline__ float2 unpack2(unsigned long long v) {
    float2 f;
    asm("mov.b64 {%0, %1}, %2;" : "=f"(f.x), "=f"(f.y) : "l"(v));
    return f;
}

// ---------------------------------------------------------------------------
// Zero the recurrent state
// ---------------------------------------------------------------------------
__global__ void init_state_kernel() {
    int i = blockIdx.x * blockDim.x + threadIdx.x;
    if (i < Bq * Hq) {
        g_h[0][0][i] = 0.f; g_h[0][1][i] = 0.f;
        g_h[1][0][i] = 0.f; g_h[1][1][i] = 0.f;
        g_c[0][i]    = 0.f; g_c[1][i]    = 0.f;
    }
}

// ---------------------------------------------------------------------------
// Generic tiled GEMM:  C[M,N] = A[M,K] @ B[K,N] + bias[N]
// 128x128 tile, BK=16, 256 threads, per-thread 8x8 (rows packed for f32x2).
// Requires M%128==0, N%128==0, K%16==0.
// ---------------------------------------------------------------------------
__global__ __launch_bounds__(256) void gemm_bias_kernel(
    const float* __restrict__ A, const float* __restrict__ B,
    const float* __restrict__ bias, float* __restrict__ C,
    int M, int N, int K)
{
    __shared__ float As[16][128];   // [k][row]
    __shared__ float Bs[16][128];   // [k][col]

    const int tid = threadIdx.x;
    const int n0  = blockIdx.x * 128;
    const int m0  = blockIdx.y * 128;

    // global-load mapping
    const int a_kq = tid & 3;        // which float4 in the 16-wide K chunk
    const int a_r  = tid >> 2;       // row 0..63 (second pass +64)
    const int b_c4 = tid & 31;       // float4 column
    const int b_k  = tid >> 5;       // k 0..7 (second pass +8)

    // compute mapping: 16x16 thread grid, 8 rows x 8 cols each
    const int trow = tid >> 4;       // 0..15
    const int tcol = tid & 15;       // 0..15

    unsigned long long acc[4][8];
#pragma unroll
    for (int i = 0; i < 4; i++)
#pragma unroll
        for (int j = 0; j < 8; j++) acc[i][j] = 0ull;

    float4 pa0, pa1, pb0, pb1;
    pa0 = *reinterpret_cast<const float4*>(&A[(m0 + a_r)      * K + a_kq * 4]);
    pa1 = *reinterpret_cast<const float4*>(&A[(m0 + a_r + 64) * K + a_kq * 4]);
    pb0 = *reinterpret_cast<const float4*>(&B[(b_k)     * N + n0 + b_c4 * 4]);
    pb1 = *reinterpret_cast<const float4*>(&B[(b_k + 8) * N + n0 + b_c4 * 4]);

    for (int kc = 0; kc < K; kc += 16) {
        As[a_kq * 4 + 0][a_r] = pa0.x;
        As[a_kq * 4 + 1][a_r] = pa0.y;
        As[a_kq * 4 + 2][a_r] = pa0.z;
        As[a_kq * 4 + 3][a_r] = pa0.w;
        As[a_kq * 4 + 0][a_r + 64] = pa1.x;
        As[a_kq * 4 + 1][a_r + 64] = pa1.y;
        As[a_kq * 4 + 2][a_r + 64] = pa1.z;
        As[a_kq * 4 + 3][a_r + 64] = pa1.w;
        *reinterpret_cast<float4*>(&Bs[b_k][b_c4 * 4])     = pb0;
        *reinterpret_cast<float4*>(&Bs[b_k + 8][b_c4 * 4]) = pb1;
        __syncthreads();

        const int kn = kc + 16;
        if (kn < K) {
            pa0 = *reinterpret_cast<const float4*>(&A[(m0 + a_r)      * K + kn + a_kq * 4]);
            pa1 = *reinterpret_cast<const float4*>(&A[(m0 + a_r + 64) * K + kn + a_kq * 4]);
            pb0 = *reinterpret_cast<const float4*>(&B[(kn + b_k)     * N + n0 + b_c4 * 4]);
            pb1 = *reinterpret_cast<const float4*>(&B[(kn + b_k + 8) * N + n0 + b_c4 * 4]);
        }

#pragma unroll
        for (int k = 0; k < 16; k++) {
            const ulonglong2* ap =
                reinterpret_cast<const ulonglong2*>(&As[k][trow * 8]);
            ulonglong2 av0 = ap[0];
            ulonglong2 av1 = ap[1];
            unsigned long long a4[4] = {av0.x, av0.y, av1.x, av1.y};

            float4 bv0 = *reinterpret_cast<const float4*>(&Bs[k][tcol * 8]);
            float4 bv1 = *reinterpret_cast<const float4*>(&Bs[k][tcol * 8 + 4]);
            unsigned long long bd[8];
            bd[0] = dup2(bv0.x); bd[1] = dup2(bv0.y);
            bd[2] = dup2(bv0.z); bd[3] = dup2(bv0.w);
            bd[4] = dup2(bv1.x); bd[5] = dup2(bv1.y);
            bd[6] = dup2(bv1.z); bd[7] = dup2(bv1.w);

#pragma unroll
            for (int ip = 0; ip < 4; ip++)
#pragma unroll
                for (int j = 0; j < 8; j++)
                    ffma2(acc[ip][j], a4[ip], bd[j]);
        }
        __syncthreads();
    }

    // epilogue: add bias, vectorized stores (cols contiguous per thread)
    float bsv[8];
#pragma unroll
    for (int j = 0; j < 8; j++) bsv[j] = bias[n0 + tcol * 8 + j];

#pragma unroll
    for (int ip = 0; ip < 4; ip++) {
        float2 v[8];
#pragma unroll
        for (int j = 0; j < 8; j++) v[j] = unpack2(acc[ip][j]);
        int r0 = m0 + trow * 8 + ip * 2;
        float* c0 = C + r0 * N + n0 + tcol * 8;
        float* c1 = c0 + N;
        float4 x0 = make_float4(v[0].x + bsv[0], v[1].x + bsv[1],
                                v[2].x + bsv[2], v[3].x + bsv[3]);
        float4 x1 = make_float4(v[4].x + bsv[4], v[5].x + bsv[5],
                                v[6].x + bsv[6], v[7].x + bsv[7]);
        float4 y0 = make_float4(v[0].y + bsv[0], v[1].y + bsv[1],
                                v[2].y + bsv[2], v[3].y + bsv[3]);
        float4 y1 = make_float4(v[4].y + bsv[4], v[5].y + bsv[5],
                                v[6].y + bsv[6], v[7].y + bsv[7]);
        *reinterpret_cast<float4*>(c0)     = x0;
        *reinterpret_cast<float4*>(c0 + 4) = x1;
        *reinterpret_cast<float4*>(c1)     = y0;
        *reinterpret_cast<float4*>(c1 + 4) = y1;
    }
}

// ---------------------------------------------------------------------------
// One LSTM time step, BOTH directions in one launch.
//  z = embW[tok] + h_prev @ U   (bias folded into embW)
//  gate update fused in epilogue; writes h_next, c (in place), hcat slice.
// CTA tile: 64 batch rows x 32 hidden units (x4 gates = 128 GEMM cols), K=1024.
// Grid: (H/32=32, B/64=2, dir=2) = 128 CTAs, 256 threads.
// ---------------------------------------------------------------------------
__global__ __launch_bounds__(256) void lstm_step_kernel(
    const int* __restrict__ tokens,
    const float* __restrict__ Uf,
    const float* __restrict__ Ub,
    int t)
{
    __shared__ float As[16][64];     // h tile  [k][row]
    __shared__ float Bs[16][128];    // U tile  [k][gate*32+jj]
    __shared__ float zs[64][128];    // z tile for cross-gate exchange
    __shared__ int   toks[64];

    const int tid = threadIdx.x;
    const int dir = blockIdx.z;
    const int j0  = blockIdx.x * 32;
    const int b0  = blockIdx.y * 64;

    const float* U    = dir ? Ub : Uf;
    const float* embW = dir ? g_embWb : g_embWf;
    const int s = dir ? (Sq - 1 - t) : t;

    const float* hprev = &g_h[t & 1][dir][0];
    float*       hnext = &g_h[(t + 1) & 1][dir][0];
    float*       cptr  = &g_c[dir][0];

    if (tid < 64) toks[tid] = tokens[(b0 + tid) * Sq + s];

    // global-load mapping
    const int a_kq  = tid & 3;          // float4 within K-chunk
    const int a_r   = tid >> 2;         // row 0..63
    const int b_jj4 = tid & 7;          // float4 within 32-wide gate slab
    const int b_g   = (tid >> 3) & 3;   // gate
    const int b_k   = tid >> 5;         // k 0..7 (+8 second)

    // compute mapping: 8 row-groups x 32 col-groups; 8 rows x 4 cols each
    const int trow = tid >> 5;          // 0..7
    const int tcol = tid & 31;          // 0..31

    unsigned long long acc[4][4];
#pragma unroll
    for (int i = 0; i < 4; i++)
#pragma unroll
        for (int j = 0; j < 4; j++) acc[i][j] = 0ull;

    float4 pa, pb0, pb1;
    pa  = *reinterpret_cast<const float4*>(&hprev[(b0 + a_r) * Hq + a_kq * 4]);
    pb0 = *reinterpret_cast<const float4*>(&U[(b_k)     * G4H + b_g * Hq + j0 + b_jj4 * 4]);
    pb1 = *reinterpret_cast<const float4*>(&U[(b_k + 8) * G4H + b_g * Hq + j0 + b_jj4 * 4]);

    for (int kc = 0; kc < Hq; kc += 16) {
        As[a_kq * 4 + 0][a_r] = pa.x;
        As[a_kq * 4 + 1][a_r] = pa.y;
        As[a_kq * 4 + 2][a_r] = pa.z;
        As[a_kq * 4 + 3][a_r] = pa.w;
        *reinterpret_cast<float4*>(&Bs[b_k][b_g * 32 + b_jj4 * 4])     = pb0;
        *reinterpret_cast<float4*>(&Bs[b_k + 8][b_g * 32 + b_jj4 * 4]) = pb1;
        __syncthreads();

        const int kn = kc + 16;
        if (kn < Hq) {
            pa  = *reinterpret_cast<const float4*>(&hprev[(b0 + a_r) * Hq + kn + a_kq * 4]);
            pb0 = *reinterpret_cast<const float4*>(&U[(kn + b_k)     * G4H + b_g * Hq + j0 + b_jj4 * 4]);
            pb1 = *reinterpret_cast<const float4*>(&U[(kn + b_k + 8) * G4H + b_g * Hq + j0 + b_jj4 * 4]);
        }

#pragma unroll
        for (int k = 0; k < 16; k++) {
            const ulonglong2* ap =
                reinterpret_cast<const ulonglong2*>(&As[k][trow * 8]);  // broadcast
            ulonglong2 av0 = ap[0];
            ulonglong2 av1 = ap[1];
            unsigned long long a4[4] = {av0.x, av0.y, av1.x, av1.y};

            float4 bv = *reinterpret_cast<const float4*>(&Bs[k][tcol * 4]);
            unsigned long long bd[4];
            bd[0] = dup2(bv.x); bd[1] = dup2(bv.y);
            bd[2] = dup2(bv.z); bd[3] = dup2(bv.w);

#pragma unroll
            for (int ip = 0; ip < 4; ip++)
#pragma unroll
                for (int j = 0; j < 4; j++)
                    ffma2(acc[ip][j], a4[ip], bd[j]);
        }
        __syncthreads();
    }

    // spill z to SMEM so each thread can gather all 4 gates for its (b,j)
#pragma unroll
    for (int ip = 0; ip < 4; ip++)
#pragma unroll
        for (int j = 0; j < 4; j++) {
            float2 v = unpack2(acc[ip][j]);
            zs[trow * 8 + ip * 2 + 0][tcol * 4 + j] = v.x;
            zs[trow * 8 + ip * 2 + 1][tcol * 4 + j] = v.y;
        }
    __syncthreads();

    // fused gate update: 64 rows x 32 hidden units = 2048 items, 8 per thread
#pragma unroll
    for (int it = 0; it < 8; it++) {
        int idx = it * 256 + tid;
        int r  = idx >> 5;      // 0..63
        int jj = idx & 31;      // 0..31
        int tok = toks[r];
        const float* ew = embW + tok * G4H + (j0 + jj);

        float zi = zs[r][jj]          + ew[0 * Hq];
        float zf = zs[r][32 + jj]     + ew[1 * Hq];
        float zg = zs[r][64 + jj]     + ew[2 * Hq];
        float zo = zs[r][96 + jj]     + ew[3 * Hq];

        float ig = 1.f / (1.f + expf(-zi));
        float fg = 1.f / (1.f + expf(-zf));
        float og = 1.f / (1.f + expf(-zo));
        float gg = dir ? fmaxf(zg, 0.f) : tanhf(zg);

        int ci = (b0 + r) * Hq + j0 + jj;
        float c = fg * cptr[ci] + ig * gg;
        cptr[ci] = c;
        float hc = dir ? fmaxf(c, 0.f) : tanhf(c);
        float h  = og * hc;
        hnext[ci] = h;
        g_hcat[((b0 + r) * Sq + s) * (2 * Hq) + dir * Hq + j0 + jj] = h;
    }
}

// ---------------------------------------------------------------------------
// Launch
// ---------------------------------------------------------------------------
extern "C" void kernel_launch(void* const* d_in, const int* in_sizes, int n_in,
                              void* d_out, int out_size) {
    (void)in_sizes; (void)n_in; (void)out_size;
    const int*   tokens = (const int*)  d_in[0];
    const float* emb    = (const float*)d_in[1];
    const float* Wf     = (const float*)d_in[2];
    const float* Uf     = (const float*)d_in[3];
    const float* bf     = (const float*)d_in[4];
    const float* Wb     = (const float*)d_in[5];
    const float* Ub     = (const float*)d_in[6];
    const float* bb     = (const float*)d_in[7];
    const float* Wd     = (const float*)d_in[8];
    const float* bd     = (const float*)d_in[9];
    float* out = (float*)d_out;

    float *p_embWf, *p_embWb, *p_hcat;
    cudaGetSymbolAddress((void**)&p_embWf, g_embWf);
    cudaGetSymbolAddress((void**)&p_embWb, g_embWb);
    cudaGetSymbolAddress((void**)&p_hcat,  g_hcat);

    // zero h/c state
    init_state_kernel<<<(Bq * Hq + 255) / 256, 256>>>();

    // embW = emb @ W + b   (the (emb@W)[tokens] == emb[tokens]@W trick)
    gemm_bias_kernel<<<dim3(G4H / 128, Vq / 128), 256>>>(
        emb, Wf, bf, p_embWf, Vq, G4H, Eq);
    gemm_bias_kernel<<<dim3(G4H / 128, Vq / 128), 256>>>(
        emb, Wb, bb, p_embWb, Vq, G4H, Eq);

    // 256 sequential recurrent steps (both directions per launch)
    for (int t = 0; t < Sq; t++) {
        lstm_step_kernel<<<dim3(Hq / 32, Bq / 64, 2), 256>>>(tokens, Uf, Ub, t);
    }

    // out = hcat @ Wd + bd   (blockIdx.x = N fastest -> A-panel L2 reuse)
    gemm_bias_kernel<<<dim3(Vq / 128, (Bq * Sq) / 128), 256>>>(
        p_hcat, Wd, bd, out, Bq * Sq, Vq, 2 * Hq);
}

// round 4
// speedup vs baseline: 1.4187x; 1.4187x over previous
#include <cuda_runtime.h>
#include <math.h>

// Problem dims
#define Bq   128
#define Sq   256
#define Eq   512
#define Hq   1024
#define Vq   2048
#define G4H  4096   // 4*H

// ---------------------------------------------------------------------------
// Scratch (device globals; no allocation allowed)
// Interleaved layouts use column index c = j*4 + g  (j = hidden unit, g = gate
// in Keras order i,f,g,o), so one float4 = all 4 gates of one hidden unit.
// ---------------------------------------------------------------------------
__device__ float g_Wtf[Eq * G4H];            //  8 MB: Wf gate-interleaved
__device__ float g_Wtb[Eq * G4H];            //  8 MB
__device__ float g_btf[G4H];
__device__ float g_btb[G4H];
__device__ float g_Utf[Hq * G4H];            // 16 MB: Uf gate-interleaved
__device__ float g_Utb[Hq * G4H];            // 16 MB
__device__ float g_embWtf[Vq * G4H];         // 32 MB: (emb@Wf + bf) interleaved
__device__ float g_embWtb[Vq * G4H];         // 32 MB
__device__ float g_h[2][2][Bq * Hq];         // [pingpong][dir]
__device__ float g_c[2][Bq * Hq];            // [dir]
__device__ float g_hcat[Bq * Sq * 2 * Hq];   // [B][S][2H]  (256 MB)

// ---------------------------------------------------------------------------
// f32x2 packed-FMA helpers (Blackwell fma.rn.f32x2, PTX-only)
// ---------------------------------------------------------------------------
__device__ __forceinline__ unsigned long long dup2(float x) {
    unsigned long long r;
    asm("mov.b64 %0, {%1, %1};" : "=l"(r) : "f"(x));
    return r;
}
__device__ __forceinline__ void ffma2(unsigned long long &acc,
                                      unsigned long long a,
                                      unsigned long long b) {
    asm("fma.rn.f32x2 %0, %1, %2, %0;" : "+l"(acc) : "l"(a), "l"(b));
}
__device__ __forceinline__ float2 unpack2(unsigned long long v) {
    float2 f;
    asm("mov.b64 {%0, %1}, %2;" : "=f"(f.x), "=f"(f.y) : "l"(v));
    return f;
}
__device__ __forceinline__ float sigmoidf_fast(float x) {
    return __fdividef(1.f, 1.f + __expf(-x));
}

// ---------------------------------------------------------------------------
// Zero the recurrent state
// ---------------------------------------------------------------------------
__global__ void init_state_kernel() {
    int i = blockIdx.x * blockDim.x + threadIdx.x;
    if (i < Bq * Hq) {
        g_h[0][0][i] = 0.f; g_h[0][1][i] = 0.f;
        g_h[1][0][i] = 0.f; g_h[1][1][i] = 0.f;
        g_c[0][i]    = 0.f; g_c[1][i]    = 0.f;
    }
}

// ---------------------------------------------------------------------------
// Gate-interleave the input weight matrices + biases: Wt[e][j*4+g] = W[e][g*H+j]
// ---------------------------------------------------------------------------
__global__ void interleave_W_kernel(const float* __restrict__ Wf,
                                    const float* __restrict__ Wb,
                                    const float* __restrict__ bf,
                                    const float* __restrict__ bb) {
    int idx = blockIdx.x * blockDim.x + threadIdx.x;
    if (idx < Eq * G4H) {
        int e = idx >> 12;
        int c = idx & 4095;
        int src = e * G4H + (c & 3) * Hq + (c >> 2);
        g_Wtf[idx] = Wf[src];
        g_Wtb[idx] = Wb[src];
    }
    if (idx < G4H) {
        int src = (idx & 3) * Hq + (idx >> 2);
        g_btf[idx] = bf[src];
        g_btb[idx] = bb[src];
    }
}

// Ut[k][j*4+g] = U[k][g*H+j]
__global__ void interleave_U_kernel(const float* __restrict__ Uf,
                                    const float* __restrict__ Ub) {
    int idx = blockIdx.x * blockDim.x + threadIdx.x;
    if (idx < Hq * G4H) {
        int k = idx >> 12;
        int c = idx & 4095;
        int src = k * G4H + (c & 3) * Hq + (c >> 2);
        g_Utf[idx] = Uf[src];
        g_Utb[idx] = Ub[src];
    }
}

// ---------------------------------------------------------------------------
// Generic tiled GEMM:  C[M,N] = A[M,K] @ B[K,N] + bias[N]
// 128x128 tile, BK=16, 256 threads, per-thread 8x8 (rows packed for f32x2).
// Requires M%128==0, N%128==0, K%16==0.
// ---------------------------------------------------------------------------
__global__ __launch_bounds__(256) void gemm_bias_kernel(
    const float* __restrict__ A, const float* __restrict__ B,
    const float* __restrict__ bias, float* __restrict__ C,
    int M, int N, int K)
{
    __shared__ float As[16][128];   // [k][row]
    __shared__ float Bs[16][128];   // [k][col]

    const int tid = threadIdx.x;
    const int n0  = blockIdx.x * 128;
    const int m0  = blockIdx.y * 128;

    const int a_kq = tid & 3;
    const int a_r  = tid >> 2;
    const int b_c4 = tid & 31;
    const int b_k  = tid >> 5;

    const int trow = tid >> 4;
    const int tcol = tid & 15;

    unsigned long long acc[4][8];
#pragma unroll
    for (int i = 0; i < 4; i++)
#pragma unroll
        for (int j = 0; j < 8; j++) acc[i][j] = 0ull;

    float4 pa0, pa1, pb0, pb1;
    pa0 = *reinterpret_cast<const float4*>(&A[(m0 + a_r)      * K + a_kq * 4]);
    pa1 = *reinterpret_cast<const float4*>(&A[(m0 + a_r + 64) * K + a_kq * 4]);
    pb0 = *reinterpret_cast<const float4*>(&B[(b_k)     * N + n0 + b_c4 * 4]);
    pb1 = *reinterpret_cast<const float4*>(&B[(b_k + 8) * N + n0 + b_c4 * 4]);

    for (int kc = 0; kc < K; kc += 16) {
        As[a_kq * 4 + 0][a_r] = pa0.x;
        As[a_kq * 4 + 1][a_r] = pa0.y;
        As[a_kq * 4 + 2][a_r] = pa0.z;
        As[a_kq * 4 + 3][a_r] = pa0.w;
        As[a_kq * 4 + 0][a_r + 64] = pa1.x;
        As[a_kq * 4 + 1][a_r + 64] = pa1.y;
        As[a_kq * 4 + 2][a_r + 64] = pa1.z;
        As[a_kq * 4 + 3][a_r + 64] = pa1.w;
        *reinterpret_cast<float4*>(&Bs[b_k][b_c4 * 4])     = pb0;
        *reinterpret_cast<float4*>(&Bs[b_k + 8][b_c4 * 4]) = pb1;
        __syncthreads();

        const int kn = kc + 16;
        if (kn < K) {
            pa0 = *reinterpret_cast<const float4*>(&A[(m0 + a_r)      * K + kn + a_kq * 4]);
            pa1 = *reinterpret_cast<const float4*>(&A[(m0 + a_r + 64) * K + kn + a_kq * 4]);
            pb0 = *reinterpret_cast<const float4*>(&B[(kn + b_k)     * N + n0 + b_c4 * 4]);
            pb1 = *reinterpret_cast<const float4*>(&B[(kn + b_k + 8) * N + n0 + b_c4 * 4]);
        }

#pragma unroll
        for (int k = 0; k < 16; k++) {
            const ulonglong2* ap =
                reinterpret_cast<const ulonglong2*>(&As[k][trow * 8]);
            ulonglong2 av0 = ap[0];
            ulonglong2 av1 = ap[1];
            unsigned long long a4[4] = {av0.x, av0.y, av1.x, av1.y};

            float4 bv0 = *reinterpret_cast<const float4*>(&Bs[k][tcol * 8]);
            float4 bv1 = *reinterpret_cast<const float4*>(&Bs[k][tcol * 8 + 4]);
            unsigned long long bd[8];
            bd[0] = dup2(bv0.x); bd[1] = dup2(bv0.y);
            bd[2] = dup2(bv0.z); bd[3] = dup2(bv0.w);
            bd[4] = dup2(bv1.x); bd[5] = dup2(bv1.y);
            bd[6] = dup2(bv1.z); bd[7] = dup2(bv1.w);

#pragma unroll
            for (int ip = 0; ip < 4; ip++)
#pragma unroll
                for (int j = 0; j < 8; j++)
                    ffma2(acc[ip][j], a4[ip], bd[j]);
        }
        __syncthreads();
    }

    float bsv[8];
#pragma unroll
    for (int j = 0; j < 8; j++) bsv[j] = bias[n0 + tcol * 8 + j];

#pragma unroll
    for (int ip = 0; ip < 4; ip++) {
        float2 v[8];
#pragma unroll
        for (int j = 0; j < 8; j++) v[j] = unpack2(acc[ip][j]);
        int r0 = m0 + trow * 8 + ip * 2;
        float* c0 = C + r0 * N + n0 + tcol * 8;
        float* c1 = c0 + N;
        float4 x0 = make_float4(v[0].x + bsv[0], v[1].x + bsv[1],
                                v[2].x + bsv[2], v[3].x + bsv[3]);
        float4 x1 = make_float4(v[4].x + bsv[4], v[5].x + bsv[5],
                                v[6].x + bsv[6], v[7].x + bsv[7]);
        float4 y0 = make_float4(v[0].y + bsv[0], v[1].y + bsv[1],
                                v[2].y + bsv[2], v[3].y + bsv[3]);
        float4 y1 = make_float4(v[4].y + bsv[4], v[5].y + bsv[5],
                                v[6].y + bsv[6], v[7].y + bsv[7]);
        *reinterpret_cast<float4*>(c0)     = x0;
        *reinterpret_cast<float4*>(c0 + 4) = x1;
        *reinterpret_cast<float4*>(c1)     = y0;
        *reinterpret_cast<float4*>(c1 + 4) = y1;
    }
}

// ---------------------------------------------------------------------------
// One LSTM time step, both directions, gate-interleaved weights.
//   z[b, j*4+g] = (h_prev @ Ut)[b, j*4+g] + embWt[tok_b][j*4+g]
// CTA tile: 64 batch rows x 64 interleaved cols (= 16 hidden units x 4 gates).
// Grid: (4096/64=64, 128/64=2, dir=2) = 256 CTAs, 256 threads.
// Each thread: 4 rows x 4 gate-cols of ONE hidden unit -> full gate update in
// registers, no SMEM exchange.
// ---------------------------------------------------------------------------
__global__ __launch_bounds__(256) void lstm_step_kernel(
    const int* __restrict__ tokens, int t)
{
    __shared__ float As[16][64];     // h tile  [k][row]
    __shared__ float Bs[16][64];     // Ut tile [k][col]
    __shared__ int   toks[64];

    const int tid = threadIdx.x;
    const int dir = blockIdx.z;
    const int c0  = blockIdx.x * 64;   // interleaved col base (hidden base = c0/4)
    const int b0  = blockIdx.y * 64;

    const float* U    = dir ? g_Utb    : g_Utf;
    const float* embW = dir ? g_embWtb : g_embWtf;
    const int s = dir ? (Sq - 1 - t) : t;

    const float* hprev = &g_h[t & 1][dir][0];
    float*       hnext = &g_h[(t + 1) & 1][dir][0];
    float*       cptr  = &g_c[dir][0];

    if (tid < 64) toks[tid] = tokens[(b0 + tid) * Sq + s];

    // global-load mapping
    const int a_kq = tid & 3;          // float4 within 16-wide K chunk
    const int a_r  = tid >> 2;         // row 0..63
    const int b_c4 = tid & 15;         // float4 column (16 quads = 64 cols)
    const int b_k  = tid >> 4;         // k 0..15

    // compute mapping: 16 row-groups (4 rows) x 16 hidden units
    const int trow = tid >> 4;         // 0..15
    const int tcol = tid & 15;         // hidden unit within tile

    unsigned long long acc[2][4];      // [row-pair][gate]
#pragma unroll
    for (int p = 0; p < 2; p++)
#pragma unroll
        for (int g = 0; g < 4; g++) acc[p][g] = 0ull;

    float4 pa, pb;
    pa = *reinterpret_cast<const float4*>(&hprev[(b0 + a_r) * Hq + a_kq * 4]);
    pb = *reinterpret_cast<const float4*>(&U[b_k * G4H + c0 + b_c4 * 4]);

    for (int kc = 0; kc < Hq; kc += 16) {
        As[a_kq * 4 + 0][a_r] = pa.x;
        As[a_kq * 4 + 1][a_r] = pa.y;
        As[a_kq * 4 + 2][a_r] = pa.z;
        As[a_kq * 4 + 3][a_r] = pa.w;
        *reinterpret_cast<float4*>(&Bs[b_k][b_c4 * 4]) = pb;
        __syncthreads();

        const int kn = kc + 16;
        if (kn < Hq) {
            pa = *reinterpret_cast<const float4*>(&hprev[(b0 + a_r) * Hq + kn + a_kq * 4]);
            pb = *reinterpret_cast<const float4*>(&U[(kn + b_k) * G4H + c0 + b_c4 * 4]);
        }

#pragma unroll
        for (int k = 0; k < 16; k++) {
            ulonglong2 a2 =
                *reinterpret_cast<const ulonglong2*>(&As[k][trow * 4]);  // rows r..r+3
            float4 bv = *reinterpret_cast<const float4*>(&Bs[k][tcol * 4]);
            unsigned long long bd[4];
            bd[0] = dup2(bv.x); bd[1] = dup2(bv.y);
            bd[2] = dup2(bv.z); bd[3] = dup2(bv.w);
#pragma unroll
            for (int g = 0; g < 4; g++) {
                ffma2(acc[0][g], a2.x, bd[g]);
                ffma2(acc[1][g], a2.y, bd[g]);
            }
        }
        __syncthreads();
    }

    // Epilogue: gates live entirely in this thread's registers.
    const int j = (c0 >> 2) + tcol;    // global hidden index

#pragma unroll
    for (int p = 0; p < 2; p++) {
        float2 vi = unpack2(acc[p][0]);
        float2 vf = unpack2(acc[p][1]);
        float2 vg = unpack2(acc[p][2]);
        float2 vo = unpack2(acc[p][3]);
#pragma unroll
        for (int h2 = 0; h2 < 2; h2++) {
            int r = trow * 4 + p * 2 + h2;
            float zi = h2 ? vi.y : vi.x;
            float zf = h2 ? vf.y : vf.x;
            float zg = h2 ? vg.y : vg.x;
            float zo = h2 ? vo.y : vo.x;

            int tok = toks[r];
            float4 ew = *reinterpret_cast<const float4*>(&embW[tok * G4H + (j << 2)]);
            zi += ew.x; zf += ew.y; zg += ew.z; zo += ew.w;

            float ig = sigmoidf_fast(zi);
            float fg = sigmoidf_fast(zf);
            float og = sigmoidf_fast(zo);
            float gg = dir ? fmaxf(zg, 0.f) : tanhf(zg);

            int ci = (b0 + r) * Hq + j;
            float c = fg * cptr[ci] + ig * gg;
            cptr[ci] = c;
            float hc = dir ? fmaxf(c, 0.f) : tanhf(c);
            float hv = og * hc;
            hnext[ci] = hv;
            g_hcat[((b0 + r) * Sq + s) * (2 * Hq) + dir * Hq + j] = hv;
        }
    }
}

// ---------------------------------------------------------------------------
// Launch
// ---------------------------------------------------------------------------
extern "C" void kernel_launch(void* const* d_in, const int* in_sizes, int n_in,
                              void* d_out, int out_size) {
    (void)in_sizes; (void)n_in; (void)out_size;
    const int*   tokens = (const int*)  d_in[0];
    const float* emb    = (const float*)d_in[1];
    const float* Wf     = (const float*)d_in[2];
    const float* Uf     = (const float*)d_in[3];
    const float* bf     = (const float*)d_in[4];
    const float* Wb     = (const float*)d_in[5];
    const float* Ub     = (const float*)d_in[6];
    const float* bb     = (const float*)d_in[7];
    const float* Wd     = (const float*)d_in[8];
    const float* bd     = (const float*)d_in[9];
    float* out = (float*)d_out;

    float *p_Wtf, *p_Wtb, *p_btf, *p_btb, *p_embWtf, *p_embWtb, *p_hcat;
    cudaGetSymbolAddress((void**)&p_Wtf,    g_Wtf);
    cudaGetSymbolAddress((void**)&p_Wtb,    g_Wtb);
    cudaGetSymbolAddress((void**)&p_btf,    g_btf);
    cudaGetSymbolAddress((void**)&p_btb,    g_btb);
    cudaGetSymbolAddress((void**)&p_embWtf, g_embWtf);
    cudaGetSymbolAddress((void**)&p_embWtb, g_embWtb);
    cudaGetSymbolAddress((void**)&p_hcat,   g_hcat);

    // zero h/c state
    init_state_kernel<<<(Bq * Hq + 255) / 256, 256>>>();

    // gate-interleave W, b, U
    interleave_W_kernel<<<(Eq * G4H + 255) / 256, 256>>>(Wf, Wb, bf, bb);
    interleave_U_kernel<<<(Hq * G4H + 255) / 256, 256>>>(Uf, Ub);

    // embWt = emb @ Wt + bt  (the (emb@W)[tokens] == emb[tokens]@W trick,
    // columns already gate-interleaved)
    gemm_bias_kernel<<<dim3(G4H / 128, Vq / 128), 256>>>(
        emb, p_Wtf, p_btf, p_embWtf, Vq, G4H, Eq);
    gemm_bias_kernel<<<dim3(G4H / 128, Vq / 128), 256>>>(
        emb, p_Wtb, p_btb, p_embWtb, Vq, G4H, Eq);

    // 256 sequential recurrent steps (both directions per launch)
    for (int t = 0; t < Sq; t++) {
        lstm_step_kernel<<<dim3(G4H / 64, Bq / 64, 2), 256>>>(tokens, t);
    }

    // out = hcat @ Wd + bd   (blockIdx.x = N fastest -> A-panel L2 reuse)
    gemm_bias_kernel<<<dim3(Vq / 128, (Bq * Sq) / 128), 256>>>(
        p_hcat, Wd, bd, out, Bq * Sq, Vq, 2 * Hq);
}